// round 11
// baseline (speedup 1.0000x reference)
#include <cuda_runtime.h>
#include <cuda_fp16.h>
#include <cstdint>

// FixedTopKLoRALinear — Round 11 (= round 10 resubmitted after infra failure):
// fp16 GEMM at CTA 128x128 / 2 CTAs per SM (96KB smem/CTA) so co-resident
// CTAs hide the per-iter barrier bubbles.
//   out = x @ W^T + bias + soft_topk(x @ A^T) @ B^T    (SCALE = 1.0)

typedef unsigned long long u64;

#define DIN   4096
#define DOUT  4096
#define MROWS 8192
#define RNK   64
#define RNK2  128
#define KTOP  16
#define KSPL  8
#define KSEG  (DIN / KSPL)                 // 512

// ---- main GEMM tiling (fp16, CTA 128x128) ----
#define BM 128
#define BN 128
#define BKS 64                             // k per sub-tile (128B row)
#define BK  128                            // k per iteration
#define KCH (DIN / BK)                     // 32
#define NIT (KCH + 1)                      // 33 (last = LoRA)
#define SA_BYTES (BM * 128)                // 16384 per sub-tile
#define SB_BYTES (BN * 128)                // 16384
#define SUB_BYTES (SA_BYTES + SB_BYTES)    // 32768
#define STG_BYTES (2 * SUB_BYTES)          // 65536 per stage (2 sub-tiles)
#define SMEMB (2 * STG_BYTES)              // 131072 total (2 stages)

// ---- kernel-1 tiling ----
#define ZSTAGES 4
#define Z_SA (128 * 128)
#define Z_SB (64 * 128)
#define Z_STG (Z_SA + Z_SB)
#define Z_SMEM (ZSTAGES * Z_STG)           // 98304
#define Z_ITERS (KSEG / BKS)               // 8

// fp16 operands
__device__ __half g_xh[(size_t)MROWS * DIN];
__device__ __half g_wh[(size_t)DOUT * DIN];
__device__ __half g_ah[(size_t)RNK * DIN];
__device__ __half g_bh[(size_t)DOUT * RNK2];
__device__ __half g_zh[(size_t)MROWS * RNK2];
__device__ float  g_zp[(size_t)KSPL * MROWS * RNK];

// ---------------------------------------------------------------------------
__device__ __forceinline__ uint32_t smem_u32(const void* p) {
    uint32_t a;
    asm("{ .reg .u64 t; cvta.to.shared.u64 t, %1; cvt.u32.u64 %0, t; }"
        : "=r"(a) : "l"(p));
    return a;
}
__device__ __forceinline__ void cpa16(uint32_t dst, const void* src) {
    asm volatile("cp.async.cg.shared.global [%0], [%1], 16;" :: "r"(dst), "l"(src));
}
__device__ __forceinline__ void cp_commit() {
    asm volatile("cp.async.commit_group;" ::: "memory");
}
__device__ __forceinline__ void cp_wait0() {
    asm volatile("cp.async.wait_group 0;" ::: "memory");
}
__device__ __forceinline__ void cp_wait2() {
    asm volatile("cp.async.wait_group 2;" ::: "memory");
}
__device__ __forceinline__ uint32_t f2h2(float lo, float hi) {
    __half2 h = __floats2half2_rn(lo, hi);
    return *reinterpret_cast<uint32_t*>(&h);
}
__device__ __forceinline__ void mmaf16(float* d, uint2 a02, uint2 a13, uint2 b) {
    asm("mma.sync.aligned.m16n8k16.row.col.f32.f16.f16.f32 "
        "{%0,%1,%2,%3}, {%4,%5,%6,%7}, {%8,%9}, {%0,%1,%2,%3};"
        : "+f"(d[0]), "+f"(d[1]), "+f"(d[2]), "+f"(d[3])
        : "r"(a02.x), "r"(a13.x), "r"(a02.y), "r"(a13.y),
          "r"(b.x), "r"(b.y));
}

// ---------------------------------------------------------------------------
// Prep kernels
// ---------------------------------------------------------------------------
__global__ __launch_bounds__(256) void prep_h_kernel(
    const float* __restrict__ in, __half* __restrict__ out, int n8)
{
    int i = blockIdx.x * blockDim.x + threadIdx.x;
    if (i >= n8) return;
    float4 a = ((const float4*)in)[2 * i];
    float4 b = ((const float4*)in)[2 * i + 1];
    uint4 o;
    o.x = f2h2(a.x, a.y); o.y = f2h2(a.z, a.w);
    o.z = f2h2(b.x, b.y); o.w = f2h2(b.z, b.w);
    *(uint4*)&out[(size_t)i * 8] = o;
}

__global__ __launch_bounds__(256) void prep_b_kernel(const float* __restrict__ in)
{
    int i = blockIdx.x * blockDim.x + threadIdx.x;
    if (i >= DOUT * 8) return;
    const int row = i >> 3, chunk = i & 7;
    const float4 a = ((const float4*)in)[(size_t)row * (RNK / 4) + 2 * chunk];
    const float4 b = ((const float4*)in)[(size_t)row * (RNK / 4) + 2 * chunk + 1];
    uint4 o;
    o.x = f2h2(a.x, a.y); o.y = f2h2(a.z, a.w);
    o.z = f2h2(b.x, b.y); o.w = f2h2(b.z, b.w);
    *(uint4*)&g_bh[(size_t)row * RNK2 + chunk * 8] = o;
    *(uint4*)&g_bh[(size_t)row * RNK2 + 64 + chunk * 8] = make_uint4(0, 0, 0, 0);
}

// ---------------------------------------------------------------------------
// Kernel 1a: split-K partial z = x[:, seg] @ A[:, seg]^T via fp16 mma.
// ---------------------------------------------------------------------------
__global__ __launch_bounds__(256, 2) void lora_z_mma_kernel()
{
    extern __shared__ __align__(16) char sm[];
    const uint32_t sA = smem_u32(sm);

    const int tid  = threadIdx.x;
    const int lane = tid & 31;
    const int wid  = tid >> 5;
    const int wm   = wid >> 1;
    const int wn   = wid & 1;
    const int row0 = blockIdx.x * 128;
    const int kbase = blockIdx.y * KSEG;

    const int lr = tid >> 3;
    const int lc = tid & 7;
    const uint32_t swd = ((((lc >> 1) + (lr & 3)) & 3) * 32) + (lc & 1) * 16;
    const uint32_t dA = (uint32_t)lr * 128 + swd;

    const __half* pX = g_xh + (size_t)(row0 + lr) * DIN + kbase + lc * 8;
    const __half* pA = g_ah + (size_t)lr * DIN + kbase + lc * 8;

    #define Z_ISSUE(nit) do {                                                  \
        if ((nit) < Z_ITERS) {                                                 \
            const uint32_t sb = sA + ((nit) & (ZSTAGES - 1)) * Z_STG;           \
            const __half* a0 = pX + (size_t)(nit) * BKS;                       \
            const __half* b0 = pA + (size_t)(nit) * BKS;                       \
            _Pragma("unroll")                                                  \
            for (int j = 0; j < 4; ++j)                                        \
                cpa16(sb + dA + j * (32 * 128), a0 + (size_t)j * 32 * DIN);    \
            _Pragma("unroll")                                                  \
            for (int j = 0; j < 2; ++j)                                        \
                cpa16(sb + Z_SA + dA + j * (32 * 128), b0 + (size_t)j * 32 * DIN); \
        }                                                                      \
        cp_commit();                                                           \
    } while (0)

    float acc[2][4][4];
    #pragma unroll
    for (int i = 0; i < 2; ++i)
        #pragma unroll
        for (int j = 0; j < 4; ++j)
            #pragma unroll
            for (int q = 0; q < 4; ++q) acc[i][j][q] = 0.0f;

    const int g = lane >> 2;
    const int c = lane & 3;
    const char* smc = sm;

    Z_ISSUE(0);
    Z_ISSUE(1);
    Z_ISSUE(2);

    for (int it = 0; it < Z_ITERS; ++it) {
        cp_wait2();
        __syncthreads();
        Z_ISSUE(it + 3);

        const char* Ab = smc + (it & (ZSTAGES - 1)) * Z_STG;
        const char* Bb = Ab + Z_SA;
        const char* aBase = Ab + (size_t)(wm * 32 + g) * 128 + c * 8;
        const char* bBase = Bb + (size_t)(wn * 32 + g) * 128 + c * 8;

        #pragma unroll
        for (int s = 0; s < 4; ++s) {
            const int sw = ((s + g) & 3) * 32;
            uint2 af[2][2], bf[4];
            #pragma unroll
            for (int mi = 0; mi < 2; ++mi) {
                af[mi][0] = *(const uint2*)(aBase + mi * (16 * 128) + sw);
                af[mi][1] = *(const uint2*)(aBase + mi * (16 * 128) + 8 * 128 + sw);
            }
            #pragma unroll
            for (int nj = 0; nj < 4; ++nj)
                bf[nj] = *(const uint2*)(bBase + nj * (8 * 128) + sw);
            #pragma unroll
            for (int mi = 0; mi < 2; ++mi)
                #pragma unroll
                for (int nj = 0; nj < 4; ++nj)
                    mmaf16(acc[mi][nj], af[mi][0], af[mi][1], bf[nj]);
        }
    }

    float* zp = g_zp + (size_t)blockIdx.y * MROWS * RNK;
    #pragma unroll
    for (int mi = 0; mi < 2; ++mi) {
        const int r = row0 + wm * 32 + mi * 16 + g;
        #pragma unroll
        for (int nj = 0; nj < 4; ++nj) {
            const int cg = wn * 32 + nj * 8 + c * 2;
            float2 o0, o1;
            o0.x = acc[mi][nj][0]; o0.y = acc[mi][nj][1];
            o1.x = acc[mi][nj][2]; o1.y = acc[mi][nj][3];
            *(float2*)&zp[(size_t)r * RNK + cg]       = o0;
            *(float2*)&zp[(size_t)(r + 8) * RNK + cg] = o1;
        }
    }
}

// ---------------------------------------------------------------------------
// Kernel 1b: reduce 8 partials + exact soft top-k, write fp16 g_zh (padded).
// ---------------------------------------------------------------------------
__global__ __launch_bounds__(256) void lora_topk_kernel()
{
    const int tid  = threadIdx.x;
    const int wid  = tid >> 5;
    const int lane = tid & 31;
    const int row0 = blockIdx.x * 64;

    for (int rr = 0; rr < 8; ++rr) {
        const int row = row0 + wid * 8 + rr;
        const size_t base = (size_t)row * RNK;
        float v0 = 0.0f, v1 = 0.0f;
        #pragma unroll
        for (int s = 0; s < KSPL; ++s) {
            const float* zp = g_zp + (size_t)s * MROWS * RNK + base;
            v0 += zp[lane];
            v1 += zp[lane + 32];
        }
        const float a0 = fabsf(v0), a1 = fabsf(v1);
        float x0 = a0, x1 = a1;
        float thr = 0.0f;
        #pragma unroll
        for (int t = 0; t < KTOP; ++t) {
            float m = fmaxf(x0, x1);
            #pragma unroll
            for (int o = 16; o > 0; o >>= 1)
                m = fmaxf(m, __shfl_xor_sync(0xffffffffu, m, o));
            thr = m;
            unsigned ball = __ballot_sync(0xffffffffu, (x0 == m) || (x1 == m));
            int leader = __ffs(ball) - 1;
            if (lane == leader) {
                if (x0 == m) x0 = -1.0f; else x1 = -1.0f;
            }
        }
        const float m0 = 1.0f / (1.0f + expf((thr - a0) * 10.0f));
        const float m1 = 1.0f / (1.0f + expf((thr - a1) * 10.0f));
        __half* zo = g_zh + (size_t)row * RNK2;
        zo[lane]      = __float2half_rn(v0 * m0);
        zo[lane + 32] = __float2half_rn(v1 * m1);
        zo[lane + 64] = __float2half_rn(0.0f);
        zo[lane + 96] = __float2half_rn(0.0f);
    }
}

// ---------------------------------------------------------------------------
// Kernel 2: fp16 mma.sync GEMM. CTA 128x128 (2 CTAs/SM), 8 warps, warp 64x32,
// BK=128 (2 sub-tiles of k64), 2-stage cp.async pipeline, 1 sync/iter.
// Iter 32 = LoRA (g_zh / g_bh, rank padded to 128).
// ---------------------------------------------------------------------------
__global__ __launch_bounds__(256, 2) void h_gemm_kernel(
    const float* __restrict__ bias, float* __restrict__ out)
{
    extern __shared__ __align__(16) char sm[];
    const uint32_t sA = smem_u32(sm);

    const int tid  = threadIdx.x;
    const int lane = tid & 31;
    const int wid  = tid >> 5;
    const int wm   = wid >> 2;            // 0..1 (64-row half)
    const int wn   = wid & 3;             // 0..3 (32-col quarter)
    const int row0 = blockIdx.y * BM;
    const int col0 = blockIdx.x * BN;

    const int lr = tid >> 3;              // 0..31
    const int lc = tid & 7;
    const uint32_t swd = ((((lc >> 1) + (lr & 3)) & 3) * 32) + (lc & 1) * 16;
    const uint32_t dA = (uint32_t)lr * 128 + swd;

    const __half* pAx = g_xh + (size_t)(row0 + lr) * DIN + lc * 8;
    const __half* pBw = g_wh + (size_t)(col0 + lr) * DIN + lc * 8;
    const __half* pAz = g_zh + (size_t)(row0 + lr) * RNK2 + lc * 8;
    const __half* pBb = g_bh + (size_t)(col0 + lr) * RNK2 + lc * 8;

    // one ISSUE = BK=128 iter = 2 sub-tiles of k64, 16 cp.async/thread
    #define ISSUE(nit) do {                                                     \
        if ((nit) < NIT) {                                                      \
            const uint32_t sb = sA + ((nit) & 1) * STG_BYTES;                   \
            if ((nit) < KCH) {                                                  \
                _Pragma("unroll")                                               \
                for (int sub = 0; sub < 2; ++sub) {                             \
                    const uint32_t st = sb + sub * SUB_BYTES;                   \
                    const __half* a0 = pAx + (size_t)(nit) * BK + sub * BKS;    \
                    const __half* b0 = pBw + (size_t)(nit) * BK + sub * BKS;    \
                    _Pragma("unroll")                                           \
                    for (int j = 0; j < 4; ++j)                                 \
                        cpa16(st + dA + j * (32 * 128), a0 + (size_t)j * 32 * DIN); \
                    _Pragma("unroll")                                           \
                    for (int j = 0; j < 4; ++j)                                 \
                        cpa16(st + SA_BYTES + dA + j * (32 * 128), b0 + (size_t)j * 32 * DIN); \
                }                                                               \
            } else {                                                            \
                _Pragma("unroll")                                               \
                for (int sub = 0; sub < 2; ++sub) {                             \
                    const uint32_t st = sb + sub * SUB_BYTES;                   \
                    const __half* a0 = pAz + sub * BKS;                         \
                    const __half* b0 = pBb + sub * BKS;                         \
                    _Pragma("unroll")                                           \
                    for (int j = 0; j < 4; ++j)                                 \
                        cpa16(st + dA + j * (32 * 128), a0 + (size_t)j * 32 * RNK2); \
                    _Pragma("unroll")                                           \
                    for (int j = 0; j < 4; ++j)                                 \
                        cpa16(st + SA_BYTES + dA + j * (32 * 128), b0 + (size_t)j * 32 * RNK2); \
                }                                                               \
            }                                                                   \
        }                                                                       \
        cp_commit();                                                            \
    } while (0)

    float acc[4][4][4];
    #pragma unroll
    for (int i = 0; i < 4; ++i)
        #pragma unroll
        for (int j = 0; j < 4; ++j)
            #pragma unroll
            for (int q = 0; q < 4; ++q) acc[i][j][q] = 0.0f;

    const int g = lane >> 2;
    const int c = lane & 3;
    const char* smc = sm;

    ISSUE(0);

    for (int it = 0; it < NIT; ++it) {
        cp_wait0();
        __syncthreads();
        ISSUE(it + 1);

        const char* stg = smc + (it & 1) * STG_BYTES;
        const uint32_t aOff = (uint32_t)(wm * 64 + g) * 128 + c * 8;
        const uint32_t bOff = (uint32_t)(wn * 32 + g) * 128 + c * 8;

        // 8 k16-slices (2 sub-tiles x 4), single-buffered fragments
        // (2 CTAs/SM provide the cross-iteration latency hiding)
        #pragma unroll
        for (int ss = 0; ss < 8; ++ss) {
            const int sub = ss >> 2, s = ss & 3;
            const char* Ab = stg + sub * SUB_BYTES;
            const char* Bb = Ab + SA_BYTES;
            const int sw = ((s + g) & 3) * 32;
            uint2 af[4][2], bf[4];
            #pragma unroll
            for (int mi = 0; mi < 4; ++mi) {
                af[mi][0] = *(const uint2*)(Ab + aOff + mi * (16 * 128) + sw);
                af[mi][1] = *(const uint2*)(Ab + aOff + mi * (16 * 128) + 8 * 128 + sw);
            }
            #pragma unroll
            for (int nj = 0; nj < 4; ++nj)
                bf[nj] = *(const uint2*)(Bb + bOff + nj * (8 * 128) + sw);
            #pragma unroll
            for (int mi = 0; mi < 4; ++mi)
                #pragma unroll
                for (int nj = 0; nj < 4; ++nj)
                    mmaf16(acc[mi][nj], af[mi][0], af[mi][1], bf[nj]);
        }
    }

    #pragma unroll
    for (int mi = 0; mi < 4; ++mi) {
        const int r = row0 + wm * 64 + mi * 16 + g;
        #pragma unroll
        for (int nj = 0; nj < 4; ++nj) {
            const int cg = col0 + wn * 32 + nj * 8 + c * 2;
            const float2 bv = *(const float2*)&bias[cg];
            float2 o0, o1;
            o0.x = acc[mi][nj][0] + bv.x;  o0.y = acc[mi][nj][1] + bv.y;
            o1.x = acc[mi][nj][2] + bv.x;  o1.y = acc[mi][nj][3] + bv.y;
            *(float2*)&out[(size_t)r * DOUT + cg]       = o0;
            *(float2*)&out[(size_t)(r + 8) * DOUT + cg] = o1;
        }
    }
}

// ---------------------------------------------------------------------------
extern "C" void kernel_launch(void* const* d_in, const int* in_sizes, int n_in,
                              void* d_out, int out_size)
{
    const float* x    = (const float*)d_in[0];   // [8192, 4096]
    const float* A    = (const float*)d_in[1];   // [64, 4096]
    const float* Bm   = (const float*)d_in[2];   // [4096, 64]
    const float* W    = (const float*)d_in[3];   // [4096, 4096]
    const float* bias = (const float*)d_in[4];   // [4096]
    float* out = (float*)d_out;                  // [8192, 4096]

    __half* xp; cudaGetSymbolAddress((void**)&xp, g_xh);
    __half* wp; cudaGetSymbolAddress((void**)&wp, g_wh);
    __half* ap; cudaGetSymbolAddress((void**)&ap, g_ah);

    {
        int n8x = MROWS * DIN / 8;
        int n8w = DOUT * DIN / 8;
        int n8a = RNK * DIN / 8;
        prep_h_kernel<<<(n8x + 255) / 256, 256>>>(x, xp, n8x);
        prep_h_kernel<<<(n8w + 255) / 256, 256>>>(W, wp, n8w);
        prep_h_kernel<<<(n8a + 255) / 256, 256>>>(A, ap, n8a);
        prep_b_kernel<<<(DOUT * 8 + 255) / 256, 256>>>(Bm);
    }

    cudaFuncSetAttribute(lora_z_mma_kernel,
                         cudaFuncAttributeMaxDynamicSharedMemorySize, Z_SMEM);
    {
        dim3 gz(MROWS / 128, KSPL);   // (64, 8)
        lora_z_mma_kernel<<<gz, 256, Z_SMEM>>>();
        lora_topk_kernel<<<MROWS / 64, 256>>>();
    }

    cudaFuncSetAttribute(h_gemm_kernel,
                         cudaFuncAttributeMaxDynamicSharedMemorySize, SMEMB);
    dim3 grid(DOUT / BN, MROWS / BM);   // (32, 64) = 2048 CTAs
    h_gemm_kernel<<<grid, 256, SMEMB>>>(bias, out);
}

// round 12
// speedup vs baseline: 1.1089x; 1.1089x over previous
#include <cuda_runtime.h>
#include <cuda_fp16.h>
#include <cstdint>

// FixedTopKLoRALinear — Round 12: round-9 shape (CTA 128x256, warp 64x64)
// + SW128 XOR swizzle + ldmatrix.x4 conflict-free fragment loads.
//   out = x @ W^T + bias + soft_topk(x @ A^T) @ B^T    (SCALE = 1.0)

typedef unsigned long long u64;

#define DIN   4096
#define DOUT  4096
#define MROWS 8192
#define RNK   64
#define RNK2  128
#define KTOP  16
#define KSPL  8
#define KSEG  (DIN / KSPL)                 // 512

// ---- main GEMM tiling (fp16, CTA 128x256) ----
#define BM 128
#define BN 256
#define BKS 64                             // k per sub-tile (128B row)
#define BK  128                            // k per iteration (2 sub-tiles)
#define KCH (DIN / BK)                     // 32
#define NIT (KCH + 1)                      // 33 (last = LoRA)
#define SA_BYTES (BM * 128)                // 16384 per sub-tile
#define SB_BYTES (BN * 128)                // 32768
#define SUB_BYTES (SA_BYTES + SB_BYTES)    // 49152
#define STG_BYTES (2 * SUB_BYTES)          // 98304 per stage
#define SMEMB (2 * STG_BYTES)              // 196608

// ---- kernel-1 tiling (unchanged, validated) ----
#define ZSTAGES 4
#define Z_SA (128 * 128)
#define Z_SB (64 * 128)
#define Z_STG (Z_SA + Z_SB)
#define Z_SMEM (ZSTAGES * Z_STG)           // 98304
#define Z_ITERS (KSEG / BKS)               // 8

// fp16 operands
__device__ __half g_xh[(size_t)MROWS * DIN];
__device__ __half g_wh[(size_t)DOUT * DIN];
__device__ __half g_ah[(size_t)RNK * DIN];
__device__ __half g_bh[(size_t)DOUT * RNK2];
__device__ __half g_zh[(size_t)MROWS * RNK2];
__device__ float  g_zp[(size_t)KSPL * MROWS * RNK];

// ---------------------------------------------------------------------------
__device__ __forceinline__ uint32_t smem_u32(const void* p) {
    uint32_t a;
    asm("{ .reg .u64 t; cvta.to.shared.u64 t, %1; cvt.u32.u64 %0, t; }"
        : "=r"(a) : "l"(p));
    return a;
}
__device__ __forceinline__ void cpa16(uint32_t dst, const void* src) {
    asm volatile("cp.async.cg.shared.global [%0], [%1], 16;" :: "r"(dst), "l"(src));
}
__device__ __forceinline__ void cp_commit() {
    asm volatile("cp.async.commit_group;" ::: "memory");
}
__device__ __forceinline__ void cp_wait0() {
    asm volatile("cp.async.wait_group 0;" ::: "memory");
}
__device__ __forceinline__ void cp_wait2() {
    asm volatile("cp.async.wait_group 2;" ::: "memory");
}
__device__ __forceinline__ uint32_t f2h2(float lo, float hi) {
    __half2 h = __floats2half2_rn(lo, hi);
    return *reinterpret_cast<uint32_t*>(&h);
}
// canonical m16n8k16 fp16 mma, fp32 acc
__device__ __forceinline__ void mmaf16c(float* d, uint32_t a0, uint32_t a1,
                                        uint32_t a2, uint32_t a3,
                                        uint32_t b0, uint32_t b1) {
    asm("mma.sync.aligned.m16n8k16.row.col.f32.f16.f16.f32 "
        "{%0,%1,%2,%3}, {%4,%5,%6,%7}, {%8,%9}, {%0,%1,%2,%3};"
        : "+f"(d[0]), "+f"(d[1]), "+f"(d[2]), "+f"(d[3])
        : "r"(a0), "r"(a1), "r"(a2), "r"(a3), "r"(b0), "r"(b1));
}
// legacy permuted-consistent mma used by kernel 1a (uint2 fragments)
__device__ __forceinline__ void mmaf16(float* d, uint2 a02, uint2 a13, uint2 b) {
    asm("mma.sync.aligned.m16n8k16.row.col.f32.f16.f16.f32 "
        "{%0,%1,%2,%3}, {%4,%5,%6,%7}, {%8,%9}, {%0,%1,%2,%3};"
        : "+f"(d[0]), "+f"(d[1]), "+f"(d[2]), "+f"(d[3])
        : "r"(a02.x), "r"(a13.x), "r"(a02.y), "r"(a13.y),
          "r"(b.x), "r"(b.y));
}
__device__ __forceinline__ void ldsm4(uint32_t& r0, uint32_t& r1,
                                      uint32_t& r2, uint32_t& r3, uint32_t a) {
    asm volatile("ldmatrix.sync.aligned.m8n8.x4.shared.b16 {%0,%1,%2,%3}, [%4];"
                 : "=r"(r0), "=r"(r1), "=r"(r2), "=r"(r3) : "r"(a));
}

// ---------------------------------------------------------------------------
// Prep kernels (unchanged)
// ---------------------------------------------------------------------------
__global__ __launch_bounds__(256) void prep_h_kernel(
    const float* __restrict__ in, __half* __restrict__ out, int n8)
{
    int i = blockIdx.x * blockDim.x + threadIdx.x;
    if (i >= n8) return;
    float4 a = ((const float4*)in)[2 * i];
    float4 b = ((const float4*)in)[2 * i + 1];
    uint4 o;
    o.x = f2h2(a.x, a.y); o.y = f2h2(a.z, a.w);
    o.z = f2h2(b.x, b.y); o.w = f2h2(b.z, b.w);
    *(uint4*)&out[(size_t)i * 8] = o;
}

__global__ __launch_bounds__(256) void prep_b_kernel(const float* __restrict__ in)
{
    int i = blockIdx.x * blockDim.x + threadIdx.x;
    if (i >= DOUT * 8) return;
    const int row = i >> 3, chunk = i & 7;
    const float4 a = ((const float4*)in)[(size_t)row * (RNK / 4) + 2 * chunk];
    const float4 b = ((const float4*)in)[(size_t)row * (RNK / 4) + 2 * chunk + 1];
    uint4 o;
    o.x = f2h2(a.x, a.y); o.y = f2h2(a.z, a.w);
    o.z = f2h2(b.x, b.y); o.w = f2h2(b.z, b.w);
    *(uint4*)&g_bh[(size_t)row * RNK2 + chunk * 8] = o;
    *(uint4*)&g_bh[(size_t)row * RNK2 + 64 + chunk * 8] = make_uint4(0, 0, 0, 0);
}

// ---------------------------------------------------------------------------
// Kernel 1a: split-K partial z = x @ A^T (unchanged, validated)
// ---------------------------------------------------------------------------
__global__ __launch_bounds__(256, 2) void lora_z_mma_kernel()
{
    extern __shared__ __align__(16) char sm[];
    const uint32_t sA = smem_u32(sm);

    const int tid  = threadIdx.x;
    const int lane = tid & 31;
    const int wid  = tid >> 5;
    const int wm   = wid >> 1;
    const int wn   = wid & 1;
    const int row0 = blockIdx.x * 128;
    const int kbase = blockIdx.y * KSEG;

    const int lr = tid >> 3;
    const int lc = tid & 7;
    const uint32_t swd = ((((lc >> 1) + (lr & 3)) & 3) * 32) + (lc & 1) * 16;
    const uint32_t dA = (uint32_t)lr * 128 + swd;

    const __half* pX = g_xh + (size_t)(row0 + lr) * DIN + kbase + lc * 8;
    const __half* pA = g_ah + (size_t)lr * DIN + kbase + lc * 8;

    #define Z_ISSUE(nit) do {                                                  \
        if ((nit) < Z_ITERS) {                                                 \
            const uint32_t sb = sA + ((nit) & (ZSTAGES - 1)) * Z_STG;           \
            const __half* a0 = pX + (size_t)(nit) * BKS;                       \
            const __half* b0 = pA + (size_t)(nit) * BKS;                       \
            _Pragma("unroll")                                                  \
            for (int j = 0; j < 4; ++j)                                        \
                cpa16(sb + dA + j * (32 * 128), a0 + (size_t)j * 32 * DIN);    \
            _Pragma("unroll")                                                  \
            for (int j = 0; j < 2; ++j)                                        \
                cpa16(sb + Z_SA + dA + j * (32 * 128), b0 + (size_t)j * 32 * DIN); \
        }                                                                      \
        cp_commit();                                                           \
    } while (0)

    float acc[2][4][4];
    #pragma unroll
    for (int i = 0; i < 2; ++i)
        #pragma unroll
        for (int j = 0; j < 4; ++j)
            #pragma unroll
            for (int q = 0; q < 4; ++q) acc[i][j][q] = 0.0f;

    const int g = lane >> 2;
    const int c = lane & 3;
    const char* smc = sm;

    Z_ISSUE(0);
    Z_ISSUE(1);
    Z_ISSUE(2);

    for (int it = 0; it < Z_ITERS; ++it) {
        cp_wait2();
        __syncthreads();
        Z_ISSUE(it + 3);

        const char* Ab = smc + (it & (ZSTAGES - 1)) * Z_STG;
        const char* Bb = Ab + Z_SA;
        const char* aBase = Ab + (size_t)(wm * 32 + g) * 128 + c * 8;
        const char* bBase = Bb + (size_t)(wn * 32 + g) * 128 + c * 8;

        #pragma unroll
        for (int s = 0; s < 4; ++s) {
            const int sw = ((s + g) & 3) * 32;
            uint2 af[2][2], bf[4];
            #pragma unroll
            for (int mi = 0; mi < 2; ++mi) {
                af[mi][0] = *(const uint2*)(aBase + mi * (16 * 128) + sw);
                af[mi][1] = *(const uint2*)(aBase + mi * (16 * 128) + 8 * 128 + sw);
            }
            #pragma unroll
            for (int nj = 0; nj < 4; ++nj)
                bf[nj] = *(const uint2*)(bBase + nj * (8 * 128) + sw);
            #pragma unroll
            for (int mi = 0; mi < 2; ++mi)
                #pragma unroll
                for (int nj = 0; nj < 4; ++nj)
                    mmaf16(acc[mi][nj], af[mi][0], af[mi][1], bf[nj]);
        }
    }

    float* zp = g_zp + (size_t)blockIdx.y * MROWS * RNK;
    #pragma unroll
    for (int mi = 0; mi < 2; ++mi) {
        const int r = row0 + wm * 32 + mi * 16 + g;
        #pragma unroll
        for (int nj = 0; nj < 4; ++nj) {
            const int cg = wn * 32 + nj * 8 + c * 2;
            float2 o0, o1;
            o0.x = acc[mi][nj][0]; o0.y = acc[mi][nj][1];
            o1.x = acc[mi][nj][2]; o1.y = acc[mi][nj][3];
            *(float2*)&zp[(size_t)r * RNK + cg]       = o0;
            *(float2*)&zp[(size_t)(r + 8) * RNK + cg] = o1;
        }
    }
}

// ---------------------------------------------------------------------------
// Kernel 1b: reduce 8 partials + exact soft top-k (unchanged)
// ---------------------------------------------------------------------------
__global__ __launch_bounds__(256) void lora_topk_kernel()
{
    const int tid  = threadIdx.x;
    const int wid  = tid >> 5;
    const int lane = tid & 31;
    const int row0 = blockIdx.x * 64;

    for (int rr = 0; rr < 8; ++rr) {
        const int row = row0 + wid * 8 + rr;
        const size_t base = (size_t)row * RNK;
        float v0 = 0.0f, v1 = 0.0f;
        #pragma unroll
        for (int s = 0; s < KSPL; ++s) {
            const float* zp = g_zp + (size_t)s * MROWS * RNK + base;
            v0 += zp[lane];
            v1 += zp[lane + 32];
        }
        const float a0 = fabsf(v0), a1 = fabsf(v1);
        float x0 = a0, x1 = a1;
        float thr = 0.0f;
        #pragma unroll
        for (int t = 0; t < KTOP; ++t) {
            float m = fmaxf(x0, x1);
            #pragma unroll
            for (int o = 16; o > 0; o >>= 1)
                m = fmaxf(m, __shfl_xor_sync(0xffffffffu, m, o));
            thr = m;
            unsigned ball = __ballot_sync(0xffffffffu, (x0 == m) || (x1 == m));
            int leader = __ffs(ball) - 1;
            if (lane == leader) {
                if (x0 == m) x0 = -1.0f; else x1 = -1.0f;
            }
        }
        const float m0 = 1.0f / (1.0f + expf((thr - a0) * 10.0f));
        const float m1 = 1.0f / (1.0f + expf((thr - a1) * 10.0f));
        __half* zo = g_zh + (size_t)row * RNK2;
        zo[lane]      = __float2half_rn(v0 * m0);
        zo[lane + 32] = __float2half_rn(v1 * m1);
        zo[lane + 64] = __float2half_rn(0.0f);
        zo[lane + 96] = __float2half_rn(0.0f);
    }
}

// ---------------------------------------------------------------------------
// Kernel 2: fp16 mma GEMM. CTA 128x256, warp 64x64, BK=128, 2-stage cp.async,
// SW128 XOR swizzle + ldmatrix.x4 conflict-free fragment loads, 1 sync/iter.
// Iter 32 = LoRA (g_zh / g_bh, rank padded to 128).
// ---------------------------------------------------------------------------
__global__ __launch_bounds__(256, 1) void h_gemm_kernel(
    const float* __restrict__ bias, float* __restrict__ out)
{
    extern __shared__ __align__(16) char sm[];
    const uint32_t sA = smem_u32(sm);

    const int tid  = threadIdx.x;
    const int lane = tid & 31;
    const int wid  = tid >> 5;
    const int wm   = wid >> 2;            // 0..1
    const int wn   = wid & 3;             // 0..3
    const int row0 = blockIdx.y * BM;
    const int col0 = blockIdx.x * BN;

    // loader: SW128 XOR swizzle (16B chunk lc -> lc ^ (row&7))
    const int lr = tid >> 3;              // 0..31
    const int lc = tid & 7;
    const uint32_t dA = (uint32_t)lr * 128 + (uint32_t)((lc ^ (lr & 7)) * 16);

    const __half* pAx = g_xh + (size_t)(row0 + lr) * DIN + lc * 8;
    const __half* pBw = g_wh + (size_t)(col0 + lr) * DIN + lc * 8;
    const __half* pAz = g_zh + (size_t)(row0 + lr) * RNK2 + lc * 8;
    const __half* pBb = g_bh + (size_t)(col0 + lr) * RNK2 + lc * 8;

    #define ISSUE(nit) do {                                                     \
        if ((nit) < NIT) {                                                      \
            const uint32_t sb = sA + ((nit) & 1) * STG_BYTES;                   \
            if ((nit) < KCH) {                                                  \
                _Pragma("unroll")                                               \
                for (int sub = 0; sub < 2; ++sub) {                             \
                    const uint32_t st = sb + sub * SUB_BYTES;                   \
                    const __half* a0 = pAx + (size_t)(nit) * BK + sub * BKS;    \
                    const __half* b0 = pBw + (size_t)(nit) * BK + sub * BKS;    \
                    _Pragma("unroll")                                           \
                    for (int j = 0; j < 4; ++j)                                 \
                        cpa16(st + dA + j * (32 * 128), a0 + (size_t)j * 32 * DIN); \
                    _Pragma("unroll")                                           \
                    for (int j = 0; j < 8; ++j)                                 \
                        cpa16(st + SA_BYTES + dA + j * (32 * 128), b0 + (size_t)j * 32 * DIN); \
                }                                                               \
            } else {                                                            \
                _Pragma("unroll")                                               \
                for (int sub = 0; sub < 2; ++sub) {                             \
                    const uint32_t st = sb + sub * SUB_BYTES;                   \
                    const __half* a0 = pAz + sub * BKS;                         \
                    const __half* b0 = pBb + sub * BKS;                         \
                    _Pragma("unroll")                                           \
                    for (int j = 0; j < 4; ++j)                                 \
                        cpa16(st + dA + j * (32 * 128), a0 + (size_t)j * 32 * RNK2); \
                    _Pragma("unroll")                                           \
                    for (int j = 0; j < 8; ++j)                                 \
                        cpa16(st + SA_BYTES + dA + j * (32 * 128), b0 + (size_t)j * 32 * RNK2); \
                }                                                               \
            }                                                                   \
        }                                                                       \
        cp_commit();                                                            \
    } while (0)

    float acc[4][8][4];
    #pragma unroll
    for (int i = 0; i < 4; ++i)
        #pragma unroll
        for (int j = 0; j < 8; ++j)
            #pragma unroll
            for (int q = 0; q < 4; ++q) acc[i][j][q] = 0.0f;

    // ldmatrix lane geometry
    const int lm = lane >> 3;             // matrix id 0..3
    const int lj = lane & 7;              // row within matrix
    // A: matrices (m&1) select row-half (+8 rows), (m>>1) selects k-half (+16B)
    const uint32_t aRowOff = (uint32_t)(wm * 64 + ((lm & 1) << 3) + lj) * 128;
    const int aKh = lm >> 1;
    // B: matrices (m>>1) select n-half (+8 rows), (m&1) selects k-half
    const uint32_t bRowOff = (uint32_t)(wn * 64 + ((lm >> 1) << 3) + lj) * 128;
    const int bKh = lm & 1;

    ISSUE(0);

    for (int it = 0; it < NIT; ++it) {
        cp_wait0();
        __syncthreads();
        ISSUE(it + 1);

        const uint32_t stg = sA + (it & 1) * STG_BYTES;

        uint32_t af[2][4][4], bf[2][4][4];

        // load fragments for k16-slice ss (0..7): sub = ss>>2, s = ss&3
        #define LOADF(buf, ss) do {                                             \
            const int sub_ = (ss) >> 2, s_ = (ss) & 3;                          \
            const uint32_t Ab_ = stg + sub_ * SUB_BYTES;                        \
            const uint32_t Bb_ = Ab_ + SA_BYTES;                                \
            const uint32_t aCh = (uint32_t)(((2 * s_ + aKh) ^ lj) * 16);        \
            const uint32_t bCh = (uint32_t)(((2 * s_ + bKh) ^ lj) * 16);        \
            _Pragma("unroll")                                                   \
            for (int mi = 0; mi < 4; ++mi)                                      \
                ldsm4(af[buf][mi][0], af[buf][mi][1], af[buf][mi][2],            \
                      af[buf][mi][3], Ab_ + aRowOff + mi * 2048 + aCh);          \
            _Pragma("unroll")                                                   \
            for (int p = 0; p < 4; ++p)                                         \
                ldsm4(bf[buf][p][0], bf[buf][p][1], bf[buf][p][2],               \
                      bf[buf][p][3], Bb_ + bRowOff + p * 2048 + bCh);            \
        } while (0)

        LOADF(0, 0);
        #pragma unroll
        for (int ss = 0; ss < 8; ++ss) {
            if (ss < 7) LOADF((ss + 1) & 1, ss + 1);
            const int b = ss & 1;
            #pragma unroll
            for (int mi = 0; mi < 4; ++mi)
                #pragma unroll
                for (int nj = 0; nj < 8; ++nj)
                    mmaf16c(acc[mi][nj],
                            af[b][mi][0], af[b][mi][1], af[b][mi][2], af[b][mi][3],
                            bf[b][nj >> 1][(nj & 1) * 2],
                            bf[b][nj >> 1][(nj & 1) * 2 + 1]);
        }
        #undef LOADF
    }

    const int g = lane >> 2;
    const int c = lane & 3;
    #pragma unroll
    for (int mi = 0; mi < 4; ++mi) {
        const int r = row0 + wm * 64 + mi * 16 + g;
        #pragma unroll
        for (int nj = 0; nj < 8; ++nj) {
            const int cg = col0 + wn * 64 + nj * 8 + c * 2;
            const float2 bv = *(const float2*)&bias[cg];
            float2 o0, o1;
            o0.x = acc[mi][nj][0] + bv.x;  o0.y = acc[mi][nj][1] + bv.y;
            o1.x = acc[mi][nj][2] + bv.x;  o1.y = acc[mi][nj][3] + bv.y;
            *(float2*)&out[(size_t)r * DOUT + cg]       = o0;
            *(float2*)&out[(size_t)(r + 8) * DOUT + cg] = o1;
        }
    }
}

// ---------------------------------------------------------------------------
extern "C" void kernel_launch(void* const* d_in, const int* in_sizes, int n_in,
                              void* d_out, int out_size)
{
    const float* x    = (const float*)d_in[0];   // [8192, 4096]
    const float* A    = (const float*)d_in[1];   // [64, 4096]
    const float* Bm   = (const float*)d_in[2];   // [4096, 64]
    const float* W    = (const float*)d_in[3];   // [4096, 4096]
    const float* bias = (const float*)d_in[4];   // [4096]
    float* out = (float*)d_out;                  // [8192, 4096]

    __half* xp; cudaGetSymbolAddress((void**)&xp, g_xh);
    __half* wp; cudaGetSymbolAddress((void**)&wp, g_wh);
    __half* ap; cudaGetSymbolAddress((void**)&ap, g_ah);

    {
        int n8x = MROWS * DIN / 8;
        int n8w = DOUT * DIN / 8;
        int n8a = RNK * DIN / 8;
        prep_h_kernel<<<(n8x + 255) / 256, 256>>>(x, xp, n8x);
        prep_h_kernel<<<(n8w + 255) / 256, 256>>>(W, wp, n8w);
        prep_h_kernel<<<(n8a + 255) / 256, 256>>>(A, ap, n8a);
        prep_b_kernel<<<(DOUT * 8 + 255) / 256, 256>>>(Bm);
    }

    cudaFuncSetAttribute(lora_z_mma_kernel,
                         cudaFuncAttributeMaxDynamicSharedMemorySize, Z_SMEM);
    {
        dim3 gz(MROWS / 128, KSPL);   // (64, 8)
        lora_z_mma_kernel<<<gz, 256, Z_SMEM>>>();
        lora_topk_kernel<<<MROWS / 64, 256>>>();
    }

    cudaFuncSetAttribute(h_gemm_kernel,
                         cudaFuncAttributeMaxDynamicSharedMemorySize, SMEMB);
    dim3 grid(DOUT / BN, MROWS / BM);   // (16, 64) = 1024 CTAs
    h_gemm_kernel<<<grid, 256, SMEMB>>>(bias, out);
}

// round 13
// speedup vs baseline: 1.1100x; 1.0009x over previous
#include <cuda_runtime.h>
#include <cuda_fp16.h>
#include <cstdint>

// FixedTopKLoRALinear — Round 12: round-9 shape (CTA 128x256, warp 64x64)
// + SW128 XOR swizzle + ldmatrix.x4 conflict-free fragment loads.
//   out = x @ W^T + bias + soft_topk(x @ A^T) @ B^T    (SCALE = 1.0)

typedef unsigned long long u64;

#define DIN   4096
#define DOUT  4096
#define MROWS 8192
#define RNK   64
#define RNK2  128
#define KTOP  16
#define KSPL  8
#define KSEG  (DIN / KSPL)                 // 512

// ---- main GEMM tiling (fp16, CTA 128x256) ----
#define BM 128
#define BN 256
#define BKS 64                             // k per sub-tile (128B row)
#define BK  128                            // k per iteration (2 sub-tiles)
#define KCH (DIN / BK)                     // 32
#define NIT (KCH + 1)                      // 33 (last = LoRA)
#define SA_BYTES (BM * 128)                // 16384 per sub-tile
#define SB_BYTES (BN * 128)                // 32768
#define SUB_BYTES (SA_BYTES + SB_BYTES)    // 49152
#define STG_BYTES (2 * SUB_BYTES)          // 98304 per stage
#define SMEMB (2 * STG_BYTES)              // 196608

// ---- kernel-1 tiling (unchanged, validated) ----
#define ZSTAGES 4
#define Z_SA (128 * 128)
#define Z_SB (64 * 128)
#define Z_STG (Z_SA + Z_SB)
#define Z_SMEM (ZSTAGES * Z_STG)           // 98304
#define Z_ITERS (KSEG / BKS)               // 8

// fp16 operands
__device__ __half g_xh[(size_t)MROWS * DIN];
__device__ __half g_wh[(size_t)DOUT * DIN];
__device__ __half g_ah[(size_t)RNK * DIN];
__device__ __half g_bh[(size_t)DOUT * RNK2];
__device__ __half g_zh[(size_t)MROWS * RNK2];
__device__ float  g_zp[(size_t)KSPL * MROWS * RNK];

// ---------------------------------------------------------------------------
__device__ __forceinline__ uint32_t smem_u32(const void* p) {
    uint32_t a;
    asm("{ .reg .u64 t; cvta.to.shared.u64 t, %1; cvt.u32.u64 %0, t; }"
        : "=r"(a) : "l"(p));
    return a;
}
__device__ __forceinline__ void cpa16(uint32_t dst, const void* src) {
    asm volatile("cp.async.cg.shared.global [%0], [%1], 16;" :: "r"(dst), "l"(src));
}
__device__ __forceinline__ void cp_commit() {
    asm volatile("cp.async.commit_group;" ::: "memory");
}
__device__ __forceinline__ void cp_wait0() {
    asm volatile("cp.async.wait_group 0;" ::: "memory");
}
__device__ __forceinline__ void cp_wait2() {
    asm volatile("cp.async.wait_group 2;" ::: "memory");
}
__device__ __forceinline__ uint32_t f2h2(float lo, float hi) {
    __half2 h = __floats2half2_rn(lo, hi);
    return *reinterpret_cast<uint32_t*>(&h);
}
// canonical m16n8k16 fp16 mma, fp32 acc
__device__ __forceinline__ void mmaf16c(float* d, uint32_t a0, uint32_t a1,
                                        uint32_t a2, uint32_t a3,
                                        uint32_t b0, uint32_t b1) {
    asm("mma.sync.aligned.m16n8k16.row.col.f32.f16.f16.f32 "
        "{%0,%1,%2,%3}, {%4,%5,%6,%7}, {%8,%9}, {%0,%1,%2,%3};"
        : "+f"(d[0]), "+f"(d[1]), "+f"(d[2]), "+f"(d[3])
        : "r"(a0), "r"(a1), "r"(a2), "r"(a3), "r"(b0), "r"(b1));
}
// legacy permuted-consistent mma used by kernel 1a (uint2 fragments)
__device__ __forceinline__ void mmaf16(float* d, uint2 a02, uint2 a13, uint2 b) {
    asm("mma.sync.aligned.m16n8k16.row.col.f32.f16.f16.f32 "
        "{%0,%1,%2,%3}, {%4,%5,%6,%7}, {%8,%9}, {%0,%1,%2,%3};"
        : "+f"(d[0]), "+f"(d[1]), "+f"(d[2]), "+f"(d[3])
        : "r"(a02.x), "r"(a13.x), "r"(a02.y), "r"(a13.y),
          "r"(b.x), "r"(b.y));
}
__device__ __forceinline__ void ldsm4(uint32_t& r0, uint32_t& r1,
                                      uint32_t& r2, uint32_t& r3, uint32_t a) {
    asm volatile("ldmatrix.sync.aligned.m8n8.x4.shared.b16 {%0,%1,%2,%3}, [%4];"
                 : "=r"(r0), "=r"(r1), "=r"(r2), "=r"(r3) : "r"(a));
}

// ---------------------------------------------------------------------------
// Prep kernels (unchanged)
// ---------------------------------------------------------------------------
__global__ __launch_bounds__(256) void prep_h_kernel(
    const float* __restrict__ in, __half* __restrict__ out, int n8)
{
    int i = blockIdx.x * blockDim.x + threadIdx.x;
    if (i >= n8) return;
    float4 a = ((const float4*)in)[2 * i];
    float4 b = ((const float4*)in)[2 * i + 1];
    uint4 o;
    o.x = f2h2(a.x, a.y); o.y = f2h2(a.z, a.w);
    o.z = f2h2(b.x, b.y); o.w = f2h2(b.z, b.w);
    *(uint4*)&out[(size_t)i * 8] = o;
}

__global__ __launch_bounds__(256) void prep_b_kernel(const float* __restrict__ in)
{
    int i = blockIdx.x * blockDim.x + threadIdx.x;
    if (i >= DOUT * 8) return;
    const int row = i >> 3, chunk = i & 7;
    const float4 a = ((const float4*)in)[(size_t)row * (RNK / 4) + 2 * chunk];
    const float4 b = ((const float4*)in)[(size_t)row * (RNK / 4) + 2 * chunk + 1];
    uint4 o;
    o.x = f2h2(a.x, a.y); o.y = f2h2(a.z, a.w);
    o.z = f2h2(b.x, b.y); o.w = f2h2(b.z, b.w);
    *(uint4*)&g_bh[(size_t)row * RNK2 + chunk * 8] = o;
    *(uint4*)&g_bh[(size_t)row * RNK2 + 64 + chunk * 8] = make_uint4(0, 0, 0, 0);
}

// ---------------------------------------------------------------------------
// Kernel 1a: split-K partial z = x @ A^T (unchanged, validated)
// ---------------------------------------------------------------------------
__global__ __launch_bounds__(256, 2) void lora_z_mma_kernel()
{
    extern __shared__ __align__(16) char sm[];
    const uint32_t sA = smem_u32(sm);

    const int tid  = threadIdx.x;
    const int lane = tid & 31;
    const int wid  = tid >> 5;
    const int wm   = wid >> 1;
    const int wn   = wid & 1;
    const int row0 = blockIdx.x * 128;
    const int kbase = blockIdx.y * KSEG;

    const int lr = tid >> 3;
    const int lc = tid & 7;
    const uint32_t swd = ((((lc >> 1) + (lr & 3)) & 3) * 32) + (lc & 1) * 16;
    const uint32_t dA = (uint32_t)lr * 128 + swd;

    const __half* pX = g_xh + (size_t)(row0 + lr) * DIN + kbase + lc * 8;
    const __half* pA = g_ah + (size_t)lr * DIN + kbase + lc * 8;

    #define Z_ISSUE(nit) do {                                                  \
        if ((nit) < Z_ITERS) {                                                 \
            const uint32_t sb = sA + ((nit) & (ZSTAGES - 1)) * Z_STG;           \
            const __half* a0 = pX + (size_t)(nit) * BKS;                       \
            const __half* b0 = pA + (size_t)(nit) * BKS;                       \
            _Pragma("unroll")                                                  \
            for (int j = 0; j < 4; ++j)                                        \
                cpa16(sb + dA + j * (32 * 128), a0 + (size_t)j * 32 * DIN);    \
            _Pragma("unroll")                                                  \
            for (int j = 0; j < 2; ++j)                                        \
                cpa16(sb + Z_SA + dA + j * (32 * 128), b0 + (size_t)j * 32 * DIN); \
        }                                                                      \
        cp_commit();                                                           \
    } while (0)

    float acc[2][4][4];
    #pragma unroll
    for (int i = 0; i < 2; ++i)
        #pragma unroll
        for (int j = 0; j < 4; ++j)
            #pragma unroll
            for (int q = 0; q < 4; ++q) acc[i][j][q] = 0.0f;

    const int g = lane >> 2;
    const int c = lane & 3;
    const char* smc = sm;

    Z_ISSUE(0);
    Z_ISSUE(1);
    Z_ISSUE(2);

    for (int it = 0; it < Z_ITERS; ++it) {
        cp_wait2();
        __syncthreads();
        Z_ISSUE(it + 3);

        const char* Ab = smc + (it & (ZSTAGES - 1)) * Z_STG;
        const char* Bb = Ab + Z_SA;
        const char* aBase = Ab + (size_t)(wm * 32 + g) * 128 + c * 8;
        const char* bBase = Bb + (size_t)(wn * 32 + g) * 128 + c * 8;

        #pragma unroll
        for (int s = 0; s < 4; ++s) {
            const int sw = ((s + g) & 3) * 32;
            uint2 af[2][2], bf[4];
            #pragma unroll
            for (int mi = 0; mi < 2; ++mi) {
                af[mi][0] = *(const uint2*)(aBase + mi * (16 * 128) + sw);
                af[mi][1] = *(const uint2*)(aBase + mi * (16 * 128) + 8 * 128 + sw);
            }
            #pragma unroll
            for (int nj = 0; nj < 4; ++nj)
                bf[nj] = *(const uint2*)(bBase + nj * (8 * 128) + sw);
            #pragma unroll
            for (int mi = 0; mi < 2; ++mi)
                #pragma unroll
                for (int nj = 0; nj < 4; ++nj)
                    mmaf16(acc[mi][nj], af[mi][0], af[mi][1], bf[nj]);
        }
    }

    float* zp = g_zp + (size_t)blockIdx.y * MROWS * RNK;
    #pragma unroll
    for (int mi = 0; mi < 2; ++mi) {
        const int r = row0 + wm * 32 + mi * 16 + g;
        #pragma unroll
        for (int nj = 0; nj < 4; ++nj) {
            const int cg = wn * 32 + nj * 8 + c * 2;
            float2 o0, o1;
            o0.x = acc[mi][nj][0]; o0.y = acc[mi][nj][1];
            o1.x = acc[mi][nj][2]; o1.y = acc[mi][nj][3];
            *(float2*)&zp[(size_t)r * RNK + cg]       = o0;
            *(float2*)&zp[(size_t)(r + 8) * RNK + cg] = o1;
        }
    }
}

// ---------------------------------------------------------------------------
// Kernel 1b: reduce 8 partials + exact soft top-k (unchanged)
// ---------------------------------------------------------------------------
__global__ __launch_bounds__(256) void lora_topk_kernel()
{
    const int tid  = threadIdx.x;
    const int wid  = tid >> 5;
    const int lane = tid & 31;
    const int row0 = blockIdx.x * 64;

    for (int rr = 0; rr < 8; ++rr) {
        const int row = row0 + wid * 8 + rr;
        const size_t base = (size_t)row * RNK;
        float v0 = 0.0f, v1 = 0.0f;
        #pragma unroll
        for (int s = 0; s < KSPL; ++s) {
            const float* zp = g_zp + (size_t)s * MROWS * RNK + base;
            v0 += zp[lane];
            v1 += zp[lane + 32];
        }
        const float a0 = fabsf(v0), a1 = fabsf(v1);
        float x0 = a0, x1 = a1;
        float thr = 0.0f;
        #pragma unroll
        for (int t = 0; t < KTOP; ++t) {
            float m = fmaxf(x0, x1);
            #pragma unroll
            for (int o = 16; o > 0; o >>= 1)
                m = fmaxf(m, __shfl_xor_sync(0xffffffffu, m, o));
            thr = m;
            unsigned ball = __ballot_sync(0xffffffffu, (x0 == m) || (x1 == m));
            int leader = __ffs(ball) - 1;
            if (lane == leader) {
                if (x0 == m) x0 = -1.0f; else x1 = -1.0f;
            }
        }
        const float m0 = 1.0f / (1.0f + expf((thr - a0) * 10.0f));
        const float m1 = 1.0f / (1.0f + expf((thr - a1) * 10.0f));
        __half* zo = g_zh + (size_t)row * RNK2;
        zo[lane]      = __float2half_rn(v0 * m0);
        zo[lane + 32] = __float2half_rn(v1 * m1);
        zo[lane + 64] = __float2half_rn(0.0f);
        zo[lane + 96] = __float2half_rn(0.0f);
    }
}

// ---------------------------------------------------------------------------
// Kernel 2: fp16 mma GEMM. CTA 128x256, warp 64x64, BK=128, 2-stage cp.async,
// SW128 XOR swizzle + ldmatrix.x4 conflict-free fragment loads, 1 sync/iter.
// Iter 32 = LoRA (g_zh / g_bh, rank padded to 128).
// ---------------------------------------------------------------------------
__global__ __launch_bounds__(256, 1) void h_gemm_kernel(
    const float* __restrict__ bias, float* __restrict__ out)
{
    extern __shared__ __align__(16) char sm[];
    const uint32_t sA = smem_u32(sm);

    const int tid  = threadIdx.x;
    const int lane = tid & 31;
    const int wid  = tid >> 5;
    const int wm   = wid >> 2;            // 0..1
    const int wn   = wid & 3;             // 0..3
    const int row0 = blockIdx.y * BM;
    const int col0 = blockIdx.x * BN;

    // loader: SW128 XOR swizzle (16B chunk lc -> lc ^ (row&7))
    const int lr = tid >> 3;              // 0..31
    const int lc = tid & 7;
    const uint32_t dA = (uint32_t)lr * 128 + (uint32_t)((lc ^ (lr & 7)) * 16);

    const __half* pAx = g_xh + (size_t)(row0 + lr) * DIN + lc * 8;
    const __half* pBw = g_wh + (size_t)(col0 + lr) * DIN + lc * 8;
    const __half* pAz = g_zh + (size_t)(row0 + lr) * RNK2 + lc * 8;
    const __half* pBb = g_bh + (size_t)(col0 + lr) * RNK2 + lc * 8;

    #define ISSUE(nit) do {                                                     \
        if ((nit) < NIT) {                                                      \
            const uint32_t sb = sA + ((nit) & 1) * STG_BYTES;                   \
            if ((nit) < KCH) {                                                  \
                _Pragma("unroll")                                               \
                for (int sub = 0; sub < 2; ++sub) {                             \
                    const uint32_t st = sb + sub * SUB_BYTES;                   \
                    const __half* a0 = pAx + (size_t)(nit) * BK + sub * BKS;    \
                    const __half* b0 = pBw + (size_t)(nit) * BK + sub * BKS;    \
                    _Pragma("unroll")                                           \
                    for (int j = 0; j < 4; ++j)                                 \
                        cpa16(st + dA + j * (32 * 128), a0 + (size_t)j * 32 * DIN); \
                    _Pragma("unroll")                                           \
                    for (int j = 0; j < 8; ++j)                                 \
                        cpa16(st + SA_BYTES + dA + j * (32 * 128), b0 + (size_t)j * 32 * DIN); \
                }                                                               \
            } else {                                                            \
                _Pragma("unroll")                                               \
                for (int sub = 0; sub < 2; ++sub) {                             \
                    const uint32_t st = sb + sub * SUB_BYTES;                   \
                    const __half* a0 = pAz + sub * BKS;                         \
                    const __half* b0 = pBb + sub * BKS;                         \
                    _Pragma("unroll")                                           \
                    for (int j = 0; j < 4; ++j)                                 \
                        cpa16(st + dA + j * (32 * 128), a0 + (size_t)j * 32 * RNK2); \
                    _Pragma("unroll")                                           \
                    for (int j = 0; j < 8; ++j)                                 \
                        cpa16(st + SA_BYTES + dA + j * (32 * 128), b0 + (size_t)j * 32 * RNK2); \
                }                                                               \
            }                                                                   \
        }                                                                       \
        cp_commit();                                                            \
    } while (0)

    float acc[4][8][4];
    #pragma unroll
    for (int i = 0; i < 4; ++i)
        #pragma unroll
        for (int j = 0; j < 8; ++j)
            #pragma unroll
            for (int q = 0; q < 4; ++q) acc[i][j][q] = 0.0f;

    // ldmatrix lane geometry
    const int lm = lane >> 3;             // matrix id 0..3
    const int lj = lane & 7;              // row within matrix
    // A: matrices (m&1) select row-half (+8 rows), (m>>1) selects k-half (+16B)
    const uint32_t aRowOff = (uint32_t)(wm * 64 + ((lm & 1) << 3) + lj) * 128;
    const int aKh = lm >> 1;
    // B: matrices (m>>1) select n-half (+8 rows), (m&1) selects k-half
    const uint32_t bRowOff = (uint32_t)(wn * 64 + ((lm >> 1) << 3) + lj) * 128;
    const int bKh = lm & 1;

    ISSUE(0);

    for (int it = 0; it < NIT; ++it) {
        cp_wait0();
        __syncthreads();
        ISSUE(it + 1);

        const uint32_t stg = sA + (it & 1) * STG_BYTES;

        uint32_t af[2][4][4], bf[2][4][4];

        // load fragments for k16-slice ss (0..7): sub = ss>>2, s = ss&3
        #define LOADF(buf, ss) do {                                             \
            const int sub_ = (ss) >> 2, s_ = (ss) & 3;                          \
            const uint32_t Ab_ = stg + sub_ * SUB_BYTES;                        \
            const uint32_t Bb_ = Ab_ + SA_BYTES;                                \
            const uint32_t aCh = (uint32_t)(((2 * s_ + aKh) ^ lj) * 16);        \
            const uint32_t bCh = (uint32_t)(((2 * s_ + bKh) ^ lj) * 16);        \
            _Pragma("unroll")                                                   \
            for (int mi = 0; mi < 4; ++mi)                                      \
                ldsm4(af[buf][mi][0], af[buf][mi][1], af[buf][mi][2],            \
                      af[buf][mi][3], Ab_ + aRowOff + mi * 2048 + aCh);          \
            _Pragma("unroll")                                                   \
            for (int p = 0; p < 4; ++p)                                         \
                ldsm4(bf[buf][p][0], bf[buf][p][1], bf[buf][p][2],               \
                      bf[buf][p][3], Bb_ + bRowOff + p * 2048 + bCh);            \
        } while (0)

        LOADF(0, 0);
        #pragma unroll
        for (int ss = 0; ss < 8; ++ss) {
            if (ss < 7) LOADF((ss + 1) & 1, ss + 1);
            const int b = ss & 1;
            #pragma unroll
            for (int mi = 0; mi < 4; ++mi)
                #pragma unroll
                for (int nj = 0; nj < 8; ++nj)
                    mmaf16c(acc[mi][nj],
                            af[b][mi][0], af[b][mi][1], af[b][mi][2], af[b][mi][3],
                            bf[b][nj >> 1][(nj & 1) * 2],
                            bf[b][nj >> 1][(nj & 1) * 2 + 1]);
        }
        #undef LOADF
    }

    const int g = lane >> 2;
    const int c = lane & 3;
    #pragma unroll
    for (int mi = 0; mi < 4; ++mi) {
        const int r = row0 + wm * 64 + mi * 16 + g;
        #pragma unroll
        for (int nj = 0; nj < 8; ++nj) {
            const int cg = col0 + wn * 64 + nj * 8 + c * 2;
            const float2 bv = *(const float2*)&bias[cg];
            float2 o0, o1;
            o0.x = acc[mi][nj][0] + bv.x;  o0.y = acc[mi][nj][1] + bv.y;
            o1.x = acc[mi][nj][2] + bv.x;  o1.y = acc[mi][nj][3] + bv.y;
            *(float2*)&out[(size_t)r * DOUT + cg]       = o0;
            *(float2*)&out[(size_t)(r + 8) * DOUT + cg] = o1;
        }
    }
}

// ---------------------------------------------------------------------------
extern "C" void kernel_launch(void* const* d_in, const int* in_sizes, int n_in,
                              void* d_out, int out_size)
{
    const float* x    = (const float*)d_in[0];   // [8192, 4096]
    const float* A    = (const float*)d_in[1];   // [64, 4096]
    const float* Bm   = (const float*)d_in[2];   // [4096, 64]
    const float* W    = (const float*)d_in[3];   // [4096, 4096]
    const float* bias = (const float*)d_in[4];   // [4096]
    float* out = (float*)d_out;                  // [8192, 4096]

    __half* xp; cudaGetSymbolAddress((void**)&xp, g_xh);
    __half* wp; cudaGetSymbolAddress((void**)&wp, g_wh);
    __half* ap; cudaGetSymbolAddress((void**)&ap, g_ah);

    {
        int n8x = MROWS * DIN / 8;
        int n8w = DOUT * DIN / 8;
        int n8a = RNK * DIN / 8;
        prep_h_kernel<<<(n8x + 255) / 256, 256>>>(x, xp, n8x);
        prep_h_kernel<<<(n8w + 255) / 256, 256>>>(W, wp, n8w);
        prep_h_kernel<<<(n8a + 255) / 256, 256>>>(A, ap, n8a);
        prep_b_kernel<<<(DOUT * 8 + 255) / 256, 256>>>(Bm);
    }

    cudaFuncSetAttribute(lora_z_mma_kernel,
                         cudaFuncAttributeMaxDynamicSharedMemorySize, Z_SMEM);
    {
        dim3 gz(MROWS / 128, KSPL);   // (64, 8)
        lora_z_mma_kernel<<<gz, 256, Z_SMEM>>>();
        lora_topk_kernel<<<MROWS / 64, 256>>>();
    }

    cudaFuncSetAttribute(h_gemm_kernel,
                         cudaFuncAttributeMaxDynamicSharedMemorySize, SMEMB);
    dim3 grid(DOUT / BN, MROWS / BM);   // (16, 64) = 1024 CTAs
    h_gemm_kernel<<<grid, 256, SMEMB>>>(bias, out);
}